// round 16
// baseline (speedup 1.0000x reference)
#include <cuda_runtime.h>
#include <cuda.h>
#include <cuda_bf16.h>
#include <cuda_fp16.h>
#include <cstdint>

// ============================================================
// MoELayer: out[t,o] = sum_e softmax(x@gw+gb)[t,e] * (x[t,:] @ W[e,:,o])
// T=8192, D_IN=D_OUT=1024, E=8.
// R16: R15 + cluster(2,2) TMA multicast — A shared across nt-pairs,
//      B shared across mt-pairs; L2 traffic halved (GEMM was L2-BW-bound).
// ============================================================

#define T_TOKENS 8192
#define DIN      1024
#define DOUT     1024
#define N_EXP    8

#define BM 256              // tokens per CTA (2 x 128 M-blocks)
#define BN 256              // out cols per CTA (2 x 128 N-blocks)
#define BK 64               // K chunk (128 B fp16 rows, SW128)

#define TILE_B   16384                    // 128 rows * 128 B
#define STAGE_B  (4 * TILE_B)             // A0 A1 B0 B1 = 64 KB
#define NSTAGE   3
#define GEMM_SMEM (1024 + NSTAGE * STAGE_B)   // 197632

// ---------------- device scratch ----------------------------------------
__device__ float   g_gates[T_TOKENS * N_EXP];
__device__ __half  g_ah[(size_t)N_EXP * T_TOKENS * DIN];   // fp16(g_e * x)  [e][t][i]
__device__ __half  g_wh16[(size_t)N_EXP * DOUT * DIN];     // fp16(W^T)      [e][o][i]

// ---------------- arch-specific feature detection ------------------------
#if defined(__CUDA_ARCH_FEAT_SM103_ALL) || defined(__CUDA_ARCH_FEAT_SM100_ALL) || defined(__CUDA_ARCH_FEAT_SM101_ALL)
#define HAVE_TCGEN05 1
#else
#define HAVE_TCGEN05 0
#endif

// ---------------- common helpers -----------------------------------------
__device__ __forceinline__ uint32_t smem_u32(const void* p) {
    uint32_t a;
    asm("{ .reg .u64 t; cvta.to.shared.u64 t, %1; cvt.u32.u64 %0, t; }"
        : "=r"(a) : "l"(p));
    return a;
}

__device__ __forceinline__ uint32_t elect_one() {
    uint32_t p;
    asm volatile("{\n\t.reg .pred P;\n\telect.sync _|P, 0xFFFFFFFF;\n\t"
                 "selp.b32 %0, 1, 0, P;\n\t}" : "=r"(p));
    return p;
}

#define MBARRIER_INIT(addr, cnt) \
    asm volatile("mbarrier.init.shared.b64 [%0], %1;" :: "r"((uint32_t)(addr)), "r"((uint32_t)(cnt)) : "memory")
#define MBARRIER_INVAL(addr) \
    asm volatile("mbarrier.inval.shared.b64 [%0];" :: "r"((uint32_t)(addr)) : "memory")
#define MBARRIER_EXPECT_TX(addr, bytes) \
    asm volatile("mbarrier.arrive.expect_tx.shared.b64 _, [%0], %1;" \
                 :: "r"((uint32_t)(addr)), "r"((uint32_t)(bytes)) : "memory")

#define MBARRIER_WAIT_PARITY(mbar_smem_addr, phase_parity) do { \
    uint32_t _mbar = (uint32_t)(mbar_smem_addr); \
    uint32_t _parity = (uint32_t)(phase_parity); \
    uint32_t _done; \
    asm volatile( \
        "{\n\t.reg .pred p;\n\t" \
        "mbarrier.try_wait.parity.acquire.cta.shared::cta.b64 p, [%1], %2;\n\t" \
        "selp.b32 %0, 1, 0, p;\n\t}" \
        : "=r"(_done) : "r"(_mbar), "r"(_parity) : "memory"); \
    if (!_done) { \
        asm volatile( \
            "{\n\t.reg .pred P1;\n\t" \
            "WAIT_LOOP_%=:\n\t" \
            "mbarrier.try_wait.parity.acquire.cta.shared::cta.b64 P1, [%0], %1, 0x989680;\n\t" \
            "@P1 bra.uni WAIT_DONE_%=;\n\t" \
            "bra.uni WAIT_LOOP_%=;\n\t" \
            "WAIT_DONE_%=:\n\t}" \
            :: "r"(_mbar), "r"(_parity) : "memory"); \
    } \
} while (0)

#define CLUSTER_SYNC() do { \
    asm volatile("barrier.cluster.arrive.aligned;" ::: "memory"); \
    asm volatile("barrier.cluster.wait.aligned;" ::: "memory"); \
} while (0)

#define TCGEN05_ALLOC(smem_addr, nCols) \
    asm volatile("tcgen05.alloc.cta_group::1.sync.aligned.shared::cta.b32 [%0], %1;" \
                 :: "r"((uint32_t)(smem_addr)), "r"((uint32_t)(nCols)) : "memory")
#define TCGEN05_DEALLOC(tmem_addr, nCols) \
    asm volatile("tcgen05.dealloc.cta_group::1.sync.aligned.b32 %0, %1;" \
                 :: "r"(tmem_addr), "r"((uint32_t)(nCols)))
#define TCGEN05_RELINQUISH() \
    asm volatile("tcgen05.relinquish_alloc_permit.cta_group::1.sync.aligned;")
#define TCGEN05_COMMIT(mbar) \
    asm volatile("tcgen05.commit.cta_group::1.mbarrier::arrive::one.shared::cluster.b64 [%0];" \
                 :: "r"((uint32_t)(mbar)) : "memory")
#define TCGEN05_COMMIT_MULTICAST(mbar, mask) \
    asm volatile("tcgen05.commit.cta_group::1.mbarrier::arrive::one.shared::cluster.multicast::cluster.b64 [%0], %1;" \
                 :: "r"((uint32_t)(mbar)), "h"((uint16_t)(mask)) : "memory")
#define TCGEN05_WAIT_LD() \
    asm volatile("tcgen05.wait::ld.sync.aligned;" ::: "memory")
#define TCGEN05_FENCE_BEFORE() \
    asm volatile("tcgen05.fence::before_thread_sync;" ::: "memory")
#define TCGEN05_FENCE_AFTER() \
    asm volatile("tcgen05.fence::after_thread_sync;" ::: "memory")

#define TCGEN05_LD_32X32B_X32(r, tmem_addr) \
    asm volatile( \
        "tcgen05.ld.sync.aligned.32x32b.x32.b32 " \
        "{%0, %1, %2, %3, %4, %5, %6, %7, " \
        " %8, %9, %10, %11, %12, %13, %14, %15, " \
        " %16, %17, %18, %19, %20, %21, %22, %23, " \
        " %24, %25, %26, %27, %28, %29, %30, %31}, [%32];" \
        : "=r"((r)[0]),  "=r"((r)[1]),  "=r"((r)[2]),  "=r"((r)[3]), \
          "=r"((r)[4]),  "=r"((r)[5]),  "=r"((r)[6]),  "=r"((r)[7]), \
          "=r"((r)[8]),  "=r"((r)[9]),  "=r"((r)[10]), "=r"((r)[11]), \
          "=r"((r)[12]), "=r"((r)[13]), "=r"((r)[14]), "=r"((r)[15]), \
          "=r"((r)[16]), "=r"((r)[17]), "=r"((r)[18]), "=r"((r)[19]), \
          "=r"((r)[20]), "=r"((r)[21]), "=r"((r)[22]), "=r"((r)[23]), \
          "=r"((r)[24]), "=r"((r)[25]), "=r"((r)[26]), "=r"((r)[27]), \
          "=r"((r)[28]), "=r"((r)[29]), "=r"((r)[30]), "=r"((r)[31]) \
        : "r"(tmem_addr))

#if HAVE_TCGEN05
__device__ __forceinline__ void mma_f16_ss(uint32_t d, uint64_t da, uint64_t db,
                                           uint32_t idesc, uint32_t en) {
    asm volatile(
        "{\n\t.reg .pred p;\n\tsetp.ne.u32 p, %4, 0;\n\t"
        "tcgen05.mma.cta_group::1.kind::f16 [%0], %1, %2, %3, {%5, %5, %5, %5}, p;\n\t}"
        :: "r"(d), "l"(da), "l"(db), "r"(idesc), "r"(en), "r"(0u) : "memory");
}
#endif

// SW128 K-major smem descriptor (layout=SW128, version=1, SBO=64, LBO=1)
__device__ __forceinline__ uint64_t make_desc_sw128(uint32_t base) {
    const uint64_t BASE =
        (uint64_t(2) << 61) | (uint64_t(1) << 46) | (uint64_t(64) << 32) | (uint64_t(1) << 16);
    return BASE | ((uint64_t)(base >> 4) & 0x3FFF);
}

// multicast 2D TMA load: delivers tile + complete_tx to same smem offset in
// every CTA whose bit is set in mask.
#define TMA2D_MCAST(dst, mapptr, cx_, cy_, bar, mask) \
    asm volatile("cp.async.bulk.tensor.2d.shared::cluster.global.tile.mbarrier::complete_tx::bytes.multicast::cluster " \
                 "[%0], [%1, {%2, %3}], [%4], %5;" \
                 :: "r"((uint32_t)(dst)), "l"(mapptr), "r"((int)(cx_)), "r"((int)(cy_)), \
                    "r"((uint32_t)(bar)), "h"((uint16_t)(mask)) : "memory")

// ---------------- mma.sync helper (baseline PTX, fp16) --------------------
__device__ __forceinline__ void mma_fp16(float* c, const uint32_t* a, const uint32_t* b) {
    asm volatile(
        "mma.sync.aligned.m16n8k16.row.col.f32.f16.f16.f32 "
        "{%0,%1,%2,%3}, {%4,%5,%6,%7}, {%8,%9}, {%0,%1,%2,%3};"
        : "+f"(c[0]), "+f"(c[1]), "+f"(c[2]), "+f"(c[3])
        : "r"(a[0]), "r"(a[1]), "r"(a[2]), "r"(a[3]), "r"(b[0]), "r"(b[1]));
}

// ---------------- kernel 1: FUSED gate softmax + prescale (R15) -----------
__global__ void gate_prescale_kernel(const float* __restrict__ x,
                                     const float* __restrict__ gw,
                                     const float* __restrict__ gb) {
    __shared__ float gwT[N_EXP * DIN];     // [e][i]  32 KB
    int tid = threadIdx.x;

    {
        const float4* g4 = (const float4*)(gw + (size_t)tid * 32);
#pragma unroll
        for (int r = 0; r < 4; r++) {
            float4 a = g4[2 * r];
            float4 b = g4[2 * r + 1];
            int i = tid * 4 + r;
            gwT[0 * DIN + i] = a.x; gwT[1 * DIN + i] = a.y;
            gwT[2 * DIN + i] = a.z; gwT[3 * DIN + i] = a.w;
            gwT[4 * DIN + i] = b.x; gwT[5 * DIN + i] = b.y;
            gwT[6 * DIN + i] = b.z; gwT[7 * DIN + i] = b.w;
        }
    }
    __syncthreads();

    int t = (blockIdx.x * blockDim.x + tid) >> 5;
    int lane = tid & 31;
    const float4* xr = (const float4*)(x + (size_t)t * DIN);

    float4 xs[4][2];
    float acc[N_EXP];
#pragma unroll
    for (int e = 0; e < N_EXP; e++) acc[e] = 0.f;

#pragma unroll
    for (int k = 0; k < 4; k++) {
        int f4i = lane * 2 + 64 * k;
        xs[k][0] = xr[f4i];
        xs[k][1] = xr[f4i + 1];
#pragma unroll
        for (int e = 0; e < N_EXP; e++) {
            const float4* gT = (const float4*)(gwT + e * DIN);
            float4 g0 = gT[f4i];
            float4 g1 = gT[f4i + 1];
            acc[e] += xs[k][0].x * g0.x + xs[k][0].y * g0.y +
                      xs[k][0].z * g0.z + xs[k][0].w * g0.w +
                      xs[k][1].x * g1.x + xs[k][1].y * g1.y +
                      xs[k][1].z * g1.z + xs[k][1].w * g1.w;
        }
    }
#pragma unroll
    for (int off = 16; off; off >>= 1)
#pragma unroll
        for (int e = 0; e < N_EXP; e++)
            acc[e] += __shfl_xor_sync(0xffffffffu, acc[e], off);

    float m = -1e30f;
#pragma unroll
    for (int e = 0; e < N_EXP; e++) { acc[e] += gb[e]; m = fmaxf(m, acc[e]); }
    float s = 0.f;
#pragma unroll
    for (int e = 0; e < N_EXP; e++) { acc[e] = __expf(acc[e] - m); s += acc[e]; }
    float inv = 1.0f / s;
#pragma unroll
    for (int e = 0; e < N_EXP; e++) acc[e] *= inv;

    if (lane == 0) {
#pragma unroll
        for (int e = 0; e < N_EXP; e++) g_gates[t * N_EXP + e] = acc[e];
    }

#pragma unroll
    for (int e = 0; e < N_EXP; e++) {
        float g = acc[e];
        uint4* dst = (uint4*)(g_ah + ((size_t)e * T_TOKENS + t) * DIN);
#pragma unroll
        for (int k = 0; k < 4; k++) {
            __half2 h0 = __floats2half2_rn(g * xs[k][0].x, g * xs[k][0].y);
            __half2 h1 = __floats2half2_rn(g * xs[k][0].z, g * xs[k][0].w);
            __half2 h2 = __floats2half2_rn(g * xs[k][1].x, g * xs[k][1].y);
            __half2 h3 = __floats2half2_rn(g * xs[k][1].z, g * xs[k][1].w);
            uint4 pk;
            pk.x = *reinterpret_cast<uint32_t*>(&h0);
            pk.y = *reinterpret_cast<uint32_t*>(&h1);
            pk.z = *reinterpret_cast<uint32_t*>(&h2);
            pk.w = *reinterpret_cast<uint32_t*>(&h3);
            dst[lane + 32 * k] = pk;
        }
    }
}

// ---------------- kernel 2: transpose + convert W to fp16 -----------------
__global__ void wsplit_fp16_kernel(const float* __restrict__ w) {
    __shared__ float tile[64][65];
    int e = blockIdx.z;
    int i0 = blockIdx.y * 64;
    int o0 = blockIdx.x * 64;
    int tid = threadIdx.x;     // 256
    const float* wb = w + ((size_t)e << 20);
#pragma unroll
    for (int j = 0; j < 16; j++) {
        int idx = j * 256 + tid;            // 0..4095
        int il = idx >> 6, ol = idx & 63;
        tile[il][ol] = wb[(size_t)(i0 + il) * DOUT + o0 + ol];
    }
    __syncthreads();
    __half* dst = g_wh16 + ((size_t)e << 20);
#pragma unroll
    for (int j = 0; j < 8; j++) {
        int idx = j * 256 + tid;            // 0..2047 half2 units
        int ol = idx >> 5, i2 = idx & 31;
        __half2 h = __floats2half2_rn(tile[2 * i2][ol], tile[2 * i2 + 1][ol]);
        *(__half2*)(dst + (size_t)(o0 + ol) * DIN + i0 + 2 * i2) = h;
    }
}

// ---------------- kernel 3: main GEMM (cluster 2x2 multicast) -------------
__global__ void __launch_bounds__(256, 1) __cluster_dims__(2, 2, 1)
moe_gemm_kernel(float* __restrict__ out,
                const __grid_constant__ CUtensorMap tm_a,
                const __grid_constant__ CUtensorMap tm_w) {
    extern __shared__ char smem[];
    int tid = threadIdx.x;
    int wid = tid >> 5;
    int lid = tid & 31;
    int nt = blockIdx.x;           // 0..3
    int mt = blockIdx.y;           // 0..31
    int t0 = mt * BM;
    int o0 = nt * BN;

#if HAVE_TCGEN05
    // ================== tcgen05 TMA multicast producer/consumer ==========
    // cluster(2,2): cx = nt&1 (N dir), cy = mt&1 (M dir), rank = cx + 2*cy.
    // A identical across the cx pair (same mt)  -> cx==0 multicasts A.
    // B identical across the cy pair (same nt)  -> cy==0 multicasts B.
    // EMPTY release: consumer tcgen05.commit.multicast to its issuers.
    const int cxr = blockIdx.x & 1;
    const int cyr = blockIdx.y & 1;
    const int rank = cxr + 2 * cyr;
    const uint16_t amask = (uint16_t)(0x3u << (2 * cyr));      // row pair
    const uint16_t bmask = (uint16_t)(0x5u << cxr);            // column pair
    const uint16_t emask = (uint16_t)((1u << rank) | (1u << (2 * cyr)) | (1u << cxr));
    const int ecnt = (rank == 0) ? 3 : (rank == 3) ? 1 : 2;    // EMPTY arrivals

    uint32_t sb = smem_u32(smem);
    const uint32_t FULL0  = sb + 8;    // full[s]  = FULL0  + 8*s
    const uint32_t EMPTY0 = sb + 32;   // empty[s] = EMPTY0 + 8*s
    const uint32_t DONE   = sb + 56;
    // fp16: dtype F32, atype/btype FP16(=0), N=128, M=128
    const uint32_t IDESC = (1u << 4) | ((128 / 8) << 17) | ((128 / 16) << 24);
    const int CHUNKS = N_EXP * (DIN / BK);     // 128

    if (wid == 0) TCGEN05_ALLOC(sb, 512);
    if (tid == 0) {
#pragma unroll
        for (int s = 0; s < NSTAGE; s++) {
            MBARRIER_INIT(FULL0 + 8 * s, 1);
            MBARRIER_INIT(EMPTY0 + 8 * s, ecnt);
        }
        MBARRIER_INIT(DONE, 1);
    }
    __syncthreads();
    // peer barriers must be initialized before any multicast targets them
    CLUSTER_SYNC();

    uint32_t tb;
    asm volatile("ld.shared.b32 %0, [%1];" : "=r"(tb) : "r"(sb));

    if (wid == 0) {
        // ---------------- producer: multicast TMA loads ----------------
        int pe[NSTAGE] = {0, 0, 0};
        for (int c = 0; c < CHUNKS; c++) {
            int s = c % NSTAGE;
            int e = c >> 4, kc = c & 15;
            if (c >= NSTAGE) { MBARRIER_WAIT_PARITY(EMPTY0 + 8 * s, pe[s]); pe[s] ^= 1; }
            if (elect_one()) {
                uint32_t sbase = sb + 1024 + (uint32_t)s * STAGE_B;
                uint32_t fb = FULL0 + 8 * s;
                int cx = kc * BK;
                int ya = e * T_TOKENS + t0;
                int yb = e * DOUT + o0;
                MBARRIER_EXPECT_TX(fb, STAGE_B);
                if (cxr == 0) {   // A issuer for the row pair
                    TMA2D_MCAST(sbase,              &tm_a, cx, ya,       fb, amask);
                    TMA2D_MCAST(sbase + 1 * TILE_B, &tm_a, cx, ya + 128, fb, amask);
                }
                if (cyr == 0) {   // B issuer for the column pair
                    TMA2D_MCAST(sbase + 2 * TILE_B, &tm_w, cx, yb,       fb, bmask);
                    TMA2D_MCAST(sbase + 3 * TILE_B, &tm_w, cx, yb + 128, fb, bmask);
                }
            }
        }
    } else if (wid == 1) {
        // ---------------- consumer: MMA issue ----------------
        int pf[NSTAGE] = {0, 0, 0};
        for (int c = 0; c < CHUNKS; c++) {
            int s = c % NSTAGE;
            MBARRIER_WAIT_PARITY(FULL0 + 8 * s, pf[s]); pf[s] ^= 1;
            if (elect_one()) {
                uint32_t sbase = sb + 1024 + (uint32_t)s * STAGE_B;
                uint64_t dA0 = make_desc_sw128(sbase);
                uint64_t dA1 = make_desc_sw128(sbase + 1 * TILE_B);
                uint64_t dB0 = make_desc_sw128(sbase + 2 * TILE_B);
                uint64_t dB1 = make_desc_sw128(sbase + 3 * TILE_B);
#pragma unroll
                for (int ks = 0; ks < 4; ks++) {
                    uint64_t off = (uint64_t)(ks * 2);     // 16 fp16 = 32 B
                    uint32_t en0 = (c == 0 && ks == 0) ? 0u : 1u;
                    mma_f16_ss(tb,             dA0 + off, dB0 + off, IDESC, en0);
                    mma_f16_ss(tb + 128,       dA0 + off, dB1 + off, IDESC, en0);
                    mma_f16_ss(tb + 256,       dA1 + off, dB0 + off, IDESC, en0);
                    mma_f16_ss(tb + 256 + 128, dA1 + off, dB1 + off, IDESC, en0);
                }
                // release stage s in every CTA that feeds us
                TCGEN05_COMMIT_MULTICAST(EMPTY0 + 8 * s, emask);
            }
        }
        if (elect_one()) TCGEN05_COMMIT(DONE);
    }
    // warps 2..7 fall through

    __syncthreads();                 // ensures DONE commit was issued
    MBARRIER_WAIT_PARITY(DONE, 0);
    TCGEN05_FENCE_AFTER();

    // epilogue: single TMEM read + store
    {
        int mblk = wid >> 2;
        int row = (wid & 3) * 32 + lid;
        int my_t = t0 + mblk * 128 + row;
        float* orow = out + (size_t)my_t * DOUT + o0;
#pragma unroll
        for (int q = 0; q < 8; q++) {
            uint32_t tmp[32];
            TCGEN05_LD_32X32B_X32(tmp, tb + mblk * 256 + q * 32);
            TCGEN05_WAIT_LD();
#pragma unroll
            for (int v = 0; v < 8; v++) {
                float4 f4 = make_float4(__uint_as_float(tmp[4 * v]),
                                        __uint_as_float(tmp[4 * v + 1]),
                                        __uint_as_float(tmp[4 * v + 2]),
                                        __uint_as_float(tmp[4 * v + 3]));
                ((float4*)(orow + q * 32))[v] = f4;
            }
        }
        TCGEN05_FENCE_BEFORE();
    }

    __syncthreads();
    // peers may still commit into our EMPTY until their last chunk; no CTA
    // may invalidate/exit while cluster peers are active.
    CLUSTER_SYNC();
    if (tid == 0) {
#pragma unroll
        for (int s = 0; s < NSTAGE; s++) {
            MBARRIER_INVAL(FULL0 + 8 * s);
            MBARRIER_INVAL(EMPTY0 + 8 * s);
        }
        MBARRIER_INVAL(DONE);
    }
    __syncthreads();
    if (wid == 0) { TCGEN05_RELINQUISH(); TCGEN05_DEALLOC(tb, 512); }

#else
    // ================== mma.sync HMMA fallback (baseline pass) ===========
    const int wr = wid >> 1;
    const int wc = wid & 1;
    const int tg = lid >> 2;
    const int tig = lid & 3;

    for (int half = 0; half < 2; half++) {
        for (int nh = 0; nh < 2; nh++) {
            int t0h = t0 + half * 128;
            int o0h = o0 + nh * 128;

            float C[64];
#pragma unroll
            for (int i = 0; i < 64; i++) C[i] = 0.f;

            auto load_chunk = [&](int s, int c) {
                int e = c >> 5, kc = c & 31;
                const uint4* A4 = (const uint4*)(g_ah + ((size_t)e * T_TOKENS + t0h) * DIN);
                const uint4* B4 = (const uint4*)(g_wh16 + ((size_t)e << 20) + (size_t)o0h * DIN);
                char* dst = smem + s * 20480;
#pragma unroll
                for (int j = 0; j < 2; j++) {
                    int idx = j * 256 + tid;          // 0..511
                    int r2 = idx >> 2;
                    int c16 = idx & 3;
                    size_t g = (size_t)r2 * 128 + kc * 4 + c16;
                    uint32_t so = (uint32_t)r2 * 80 + c16 * 16;
                    uint4 va = A4[g];
                    uint4 vb = B4[g];
                    *(uint4*)(dst + so)         = va;
                    *(uint4*)(dst + 10240 + so) = vb;
                }
            };

            auto compute = [&](int s) {
                const char* base = smem + s * 20480;
#pragma unroll
                for (int ks = 0; ks < 2; ks++) {
                    int kb = ks * 16;
                    uint32_t a[2][4];
#pragma unroll
                    for (int m2 = 0; m2 < 2; m2++) {
                        int r0 = wr * 32 + m2 * 16 + tg;
                        const char* A0 = base + (uint32_t)r0 * 80 + (kb + tig * 2) * 2;
                        a[m2][0] = *(const uint32_t*)(A0);
                        a[m2][1] = *(const uint32_t*)(A0 + 8 * 80);
                        a[m2][2] = *(const uint32_t*)(A0 + 16);
                        a[m2][3] = *(const uint32_t*)(A0 + 8 * 80 + 16);
                    }
                    uint32_t b[8][2];
#pragma unroll
                    for (int n2 = 0; n2 < 8; n2++) {
                        int nr = wc * 64 + n2 * 8 + tg;
                        const char* B0 = base + 10240 + (uint32_t)nr * 80 + (kb + tig * 2) * 2;
                        b[n2][0] = *(const uint32_t*)(B0);
                        b[n2][1] = *(const uint32_t*)(B0 + 16);
                    }
#pragma unroll
                    for (int m2 = 0; m2 < 2; m2++)
#pragma unroll
                        for (int n2 = 0; n2 < 8; n2++)
                            mma_fp16(&C[(m2 * 8 + n2) * 4], a[m2], b[n2]);
                }
            };

            load_chunk(0, 0);
            __syncthreads();
            for (int c = 0; c < 256; c++) {
                if (c < 255) load_chunk((c + 1) & 1, c + 1);
                compute(c & 1);
                __syncthreads();
            }

#pragma unroll
            for (int m2 = 0; m2 < 2; m2++)
#pragma unroll
                for (int n2 = 0; n2 < 8; n2++) {
                    int i = (m2 * 8 + n2) * 4;
                    size_t r = (size_t)(t0h + wr * 32 + m2 * 16 + tg);
                    size_t col = (size_t)(o0h + wc * 64 + n2 * 8 + tig * 2);
                    float2 v0 = make_float2(C[i + 0], C[i + 1]);
                    float2 v1 = make_float2(C[i + 2], C[i + 3]);
                    *(float2*)&out[r * DOUT + col]       = v0;
                    *(float2*)&out[(r + 8) * DOUT + col] = v1;
                }
            __syncthreads();
        }
    }
#endif
}

// ---------------- host: tensor-map setup + launch -------------------------
typedef CUresult (*EncodeTiledFn)(
    CUtensorMap*, CUtensorMapDataType, cuuint32_t, void*,
    const cuuint64_t*, const cuuint64_t*, const cuuint32_t*, const cuuint32_t*,
    CUtensorMapInterleave, CUtensorMapSwizzle, CUtensorMapL2promotion,
    CUtensorMapFloatOOBfill);

static void make_map_2d(EncodeTiledFn enc, CUtensorMap* m, void* ptr, uint64_t rows) {
    cuuint64_t dims[2]    = {(cuuint64_t)DIN, (cuuint64_t)rows};
    cuuint64_t strides[1] = {(cuuint64_t)DIN * 2};
    cuuint32_t box[2]     = {(cuuint32_t)BK, 128};   // 64 fp16 = 128 B = SW128 span
    cuuint32_t es[2]      = {1, 1};
    enc(m, CU_TENSOR_MAP_DATA_TYPE_FLOAT16, 2, ptr, dims, strides, box, es,
        CU_TENSOR_MAP_INTERLEAVE_NONE, CU_TENSOR_MAP_SWIZZLE_128B,
        CU_TENSOR_MAP_L2_PROMOTION_L2_128B, CU_TENSOR_MAP_FLOAT_OOB_FILL_NONE);
}

extern "C" void kernel_launch(void* const* d_in, const int* in_sizes, int n_in,
                              void* d_out, int out_size) {
    const float* x  = (const float*)d_in[0];
    const float* gw = (const float*)d_in[1];
    const float* gb = (const float*)d_in[2];
    const float* w  = (const float*)d_in[3];
    float* out = (float*)d_out;

    static CUtensorMap s_maps[2];
    static bool s_init = false;
    if (!s_init) {
        void* fn = nullptr;
        cudaDriverEntryPointQueryResult qr;
        cudaGetDriverEntryPoint("cuTensorMapEncodeTiled", &fn, cudaEnableDefault, &qr);
        EncodeTiledFn enc = (EncodeTiledFn)fn;
        void *pa, *pw;
        cudaGetSymbolAddress(&pa, g_ah);
        cudaGetSymbolAddress(&pw, g_wh16);
        make_map_2d(enc, &s_maps[0], pa, (uint64_t)N_EXP * T_TOKENS);
        make_map_2d(enc, &s_maps[1], pw, (uint64_t)N_EXP * DOUT);
        s_init = true;
    }

    gate_prescale_kernel<<<T_TOKENS / 8, 256>>>(x, gw, gb);
    wsplit_fp16_kernel<<<dim3(DOUT / 64, DIN / 64, N_EXP), 256>>>(w);

    cudaFuncSetAttribute(moe_gemm_kernel,
                         cudaFuncAttributeMaxDynamicSharedMemorySize, GEMM_SMEM);
    moe_gemm_kernel<<<dim3(DOUT / BN, T_TOKENS / BM), 256, GEMM_SMEM>>>(
        out, s_maps[0], s_maps[1]);
}

// round 17
// speedup vs baseline: 1.0435x; 1.0435x over previous
#include <cuda_runtime.h>
#include <cuda.h>
#include <cuda_bf16.h>
#include <cuda_fp16.h>
#include <cstdint>

// ============================================================
// MoELayer: out[t,o] = sum_e softmax(x@gw+gb)[t,e] * (x[t,:] @ W[e,:,o])
// T=8192, D_IN=D_OUT=1024, E=8.
// R17: R15 base (no cluster). Consumer streamlined: N=256 MMA dispatches
//      (8/chunk instead of 16) + hoisted stage descriptors.
// ============================================================

#define T_TOKENS 8192
#define DIN      1024
#define DOUT     1024
#define N_EXP    8

#define BM 256              // tokens per CTA (2 x 128 M-blocks)
#define BN 256              // out cols per CTA (one N=256 MMA per M-block)
#define BK 64               // K chunk (128 B fp16 rows, SW128)

#define TILE_B   16384                    // 128 rows * 128 B
#define STAGE_B  (4 * TILE_B)             // A0 A1 B0 B1 = 64 KB (B contiguous 256 rows)
#define NSTAGE   3
#define GEMM_SMEM (1024 + NSTAGE * STAGE_B)   // 197632

// ---------------- device scratch ----------------------------------------
__device__ float   g_gates[T_TOKENS * N_EXP];
__device__ __half  g_ah[(size_t)N_EXP * T_TOKENS * DIN];   // fp16(g_e * x)  [e][t][i]
__device__ __half  g_wh16[(size_t)N_EXP * DOUT * DIN];     // fp16(W^T)      [e][o][i]

// ---------------- arch-specific feature detection ------------------------
#if defined(__CUDA_ARCH_FEAT_SM103_ALL) || defined(__CUDA_ARCH_FEAT_SM100_ALL) || defined(__CUDA_ARCH_FEAT_SM101_ALL)
#define HAVE_TCGEN05 1
#else
#define HAVE_TCGEN05 0
#endif

// ---------------- common helpers -----------------------------------------
__device__ __forceinline__ uint32_t smem_u32(const void* p) {
    uint32_t a;
    asm("{ .reg .u64 t; cvta.to.shared.u64 t, %1; cvt.u32.u64 %0, t; }"
        : "=r"(a) : "l"(p));
    return a;
}

__device__ __forceinline__ uint32_t elect_one() {
    uint32_t p;
    asm volatile("{\n\t.reg .pred P;\n\telect.sync _|P, 0xFFFFFFFF;\n\t"
                 "selp.b32 %0, 1, 0, P;\n\t}" : "=r"(p));
    return p;
}

#define MBARRIER_INIT(addr, cnt) \
    asm volatile("mbarrier.init.shared.b64 [%0], %1;" :: "r"((uint32_t)(addr)), "r"((uint32_t)(cnt)) : "memory")
#define MBARRIER_INVAL(addr) \
    asm volatile("mbarrier.inval.shared.b64 [%0];" :: "r"((uint32_t)(addr)) : "memory")
#define MBARRIER_EXPECT_TX(addr, bytes) \
    asm volatile("mbarrier.arrive.expect_tx.shared.b64 _, [%0], %1;" \
                 :: "r"((uint32_t)(addr)), "r"((uint32_t)(bytes)) : "memory")

#define MBARRIER_WAIT_PARITY(mbar_smem_addr, phase_parity) do { \
    uint32_t _mbar = (uint32_t)(mbar_smem_addr); \
    uint32_t _parity = (uint32_t)(phase_parity); \
    uint32_t _done; \
    asm volatile( \
        "{\n\t.reg .pred p;\n\t" \
        "mbarrier.try_wait.parity.acquire.cta.shared::cta.b64 p, [%1], %2;\n\t" \
        "selp.b32 %0, 1, 0, p;\n\t}" \
        : "=r"(_done) : "r"(_mbar), "r"(_parity) : "memory"); \
    if (!_done) { \
        asm volatile( \
            "{\n\t.reg .pred P1;\n\t" \
            "WAIT_LOOP_%=:\n\t" \
            "mbarrier.try_wait.parity.acquire.cta.shared::cta.b64 P1, [%0], %1, 0x989680;\n\t" \
            "@P1 bra.uni WAIT_DONE_%=;\n\t" \
            "bra.uni WAIT_LOOP_%=;\n\t" \
            "WAIT_DONE_%=:\n\t}" \
            :: "r"(_mbar), "r"(_parity) : "memory"); \
    } \
} while (0)

#define TCGEN05_ALLOC(smem_addr, nCols) \
    asm volatile("tcgen05.alloc.cta_group::1.sync.aligned.shared::cta.b32 [%0], %1;" \
                 :: "r"((uint32_t)(smem_addr)), "r"((uint32_t)(nCols)) : "memory")
#define TCGEN05_DEALLOC(tmem_addr, nCols) \
    asm volatile("tcgen05.dealloc.cta_group::1.sync.aligned.b32 %0, %1;" \
                 :: "r"(tmem_addr), "r"((uint32_t)(nCols)))
#define TCGEN05_RELINQUISH() \
    asm volatile("tcgen05.relinquish_alloc_permit.cta_group::1.sync.aligned;")
#define TCGEN05_COMMIT(mbar) \
    asm volatile("tcgen05.commit.cta_group::1.mbarrier::arrive::one.shared::cluster.b64 [%0];" \
                 :: "r"((uint32_t)(mbar)) : "memory")
#define TCGEN05_WAIT_LD() \
    asm volatile("tcgen05.wait::ld.sync.aligned;" ::: "memory")
#define TCGEN05_FENCE_BEFORE() \
    asm volatile("tcgen05.fence::before_thread_sync;" ::: "memory")
#define TCGEN05_FENCE_AFTER() \
    asm volatile("tcgen05.fence::after_thread_sync;" ::: "memory")

#define TCGEN05_LD_32X32B_X32(r, tmem_addr) \
    asm volatile( \
        "tcgen05.ld.sync.aligned.32x32b.x32.b32 " \
        "{%0, %1, %2, %3, %4, %5, %6, %7, " \
        " %8, %9, %10, %11, %12, %13, %14, %15, " \
        " %16, %17, %18, %19, %20, %21, %22, %23, " \
        " %24, %25, %26, %27, %28, %29, %30, %31}, [%32];" \
        : "=r"((r)[0]),  "=r"((r)[1]),  "=r"((r)[2]),  "=r"((r)[3]), \
          "=r"((r)[4]),  "=r"((r)[5]),  "=r"((r)[6]),  "=r"((r)[7]), \
          "=r"((r)[8]),  "=r"((r)[9]),  "=r"((r)[10]), "=r"((r)[11]), \
          "=r"((r)[12]), "=r"((r)[13]), "=r"((r)[14]), "=r"((r)[15]), \
          "=r"((r)[16]), "=r"((r)[17]), "=r"((r)[18]), "=r"((r)[19]), \
          "=r"((r)[20]), "=r"((r)[21]), "=r"((r)[22]), "=r"((r)[23]), \
          "=r"((r)[24]), "=r"((r)[25]), "=r"((r)[26]), "=r"((r)[27]), \
          "=r"((r)[28]), "=r"((r)[29]), "=r"((r)[30]), "=r"((r)[31]) \
        : "r"(tmem_addr))

#if HAVE_TCGEN05
__device__ __forceinline__ void mma_f16_ss(uint32_t d, uint64_t da, uint64_t db,
                                           uint32_t idesc, uint32_t en) {
    asm volatile(
        "{\n\t.reg .pred p;\n\tsetp.ne.u32 p, %4, 0;\n\t"
        "tcgen05.mma.cta_group::1.kind::f16 [%0], %1, %2, %3, {%5, %5, %5, %5}, p;\n\t}"
        :: "r"(d), "l"(da), "l"(db), "r"(idesc), "r"(en), "r"(0u) : "memory");
}
#endif

// SW128 K-major smem descriptor (layout=SW128, version=1, SBO=64, LBO=1)
__device__ __forceinline__ uint64_t make_desc_sw128(uint32_t base) {
    const uint64_t BASE =
        (uint64_t(2) << 61) | (uint64_t(1) << 46) | (uint64_t(64) << 32) | (uint64_t(1) << 16);
    return BASE | ((uint64_t)(base >> 4) & 0x3FFF);
}

// 2D TMA load into SMEM (mbarrier complete_tx)
#define TMA2D(dst, mapptr, cx, cy, bar) \
    asm volatile("cp.async.bulk.tensor.2d.shared::cta.global.tile.mbarrier::complete_tx::bytes " \
                 "[%0], [%1, {%2, %3}], [%4];" \
                 :: "r"((uint32_t)(dst)), "l"(mapptr), "r"((int)(cx)), "r"((int)(cy)), \
                    "r"((uint32_t)(bar)) : "memory")

// ---------------- mma.sync helper (baseline PTX, fp16) --------------------
__device__ __forceinline__ void mma_fp16(float* c, const uint32_t* a, const uint32_t* b) {
    asm volatile(
        "mma.sync.aligned.m16n8k16.row.col.f32.f16.f16.f32 "
        "{%0,%1,%2,%3}, {%4,%5,%6,%7}, {%8,%9}, {%0,%1,%2,%3};"
        : "+f"(c[0]), "+f"(c[1]), "+f"(c[2]), "+f"(c[3])
        : "r"(a[0]), "r"(a[1]), "r"(a[2]), "r"(a[3]), "r"(b[0]), "r"(b[1]));
}

// ---------------- kernel 1: FUSED gate softmax + prescale (R15) -----------
__global__ void gate_prescale_kernel(const float* __restrict__ x,
                                     const float* __restrict__ gw,
                                     const float* __restrict__ gb) {
    __shared__ float gwT[N_EXP * DIN];     // [e][i]  32 KB
    int tid = threadIdx.x;

    {
        const float4* g4 = (const float4*)(gw + (size_t)tid * 32);
#pragma unroll
        for (int r = 0; r < 4; r++) {
            float4 a = g4[2 * r];
            float4 b = g4[2 * r + 1];
            int i = tid * 4 + r;
            gwT[0 * DIN + i] = a.x; gwT[1 * DIN + i] = a.y;
            gwT[2 * DIN + i] = a.z; gwT[3 * DIN + i] = a.w;
            gwT[4 * DIN + i] = b.x; gwT[5 * DIN + i] = b.y;
            gwT[6 * DIN + i] = b.z; gwT[7 * DIN + i] = b.w;
        }
    }
    __syncthreads();

    int t = (blockIdx.x * blockDim.x + tid) >> 5;
    int lane = tid & 31;
    const float4* xr = (const float4*)(x + (size_t)t * DIN);

    float4 xs[4][2];
    float acc[N_EXP];
#pragma unroll
    for (int e = 0; e < N_EXP; e++) acc[e] = 0.f;

#pragma unroll
    for (int k = 0; k < 4; k++) {
        int f4i = lane * 2 + 64 * k;
        xs[k][0] = xr[f4i];
        xs[k][1] = xr[f4i + 1];
#pragma unroll
        for (int e = 0; e < N_EXP; e++) {
            const float4* gT = (const float4*)(gwT + e * DIN);
            float4 g0 = gT[f4i];
            float4 g1 = gT[f4i + 1];
            acc[e] += xs[k][0].x * g0.x + xs[k][0].y * g0.y +
                      xs[k][0].z * g0.z + xs[k][0].w * g0.w +
                      xs[k][1].x * g1.x + xs[k][1].y * g1.y +
                      xs[k][1].z * g1.z + xs[k][1].w * g1.w;
        }
    }
#pragma unroll
    for (int off = 16; off; off >>= 1)
#pragma unroll
        for (int e = 0; e < N_EXP; e++)
            acc[e] += __shfl_xor_sync(0xffffffffu, acc[e], off);

    float m = -1e30f;
#pragma unroll
    for (int e = 0; e < N_EXP; e++) { acc[e] += gb[e]; m = fmaxf(m, acc[e]); }
    float s = 0.f;
#pragma unroll
    for (int e = 0; e < N_EXP; e++) { acc[e] = __expf(acc[e] - m); s += acc[e]; }
    float inv = 1.0f / s;
#pragma unroll
    for (int e = 0; e < N_EXP; e++) acc[e] *= inv;

    if (lane == 0) {
#pragma unroll
        for (int e = 0; e < N_EXP; e++) g_gates[t * N_EXP + e] = acc[e];
    }

#pragma unroll
    for (int e = 0; e < N_EXP; e++) {
        float g = acc[e];
        uint4* dst = (uint4*)(g_ah + ((size_t)e * T_TOKENS + t) * DIN);
#pragma unroll
        for (int k = 0; k < 4; k++) {
            __half2 h0 = __floats2half2_rn(g * xs[k][0].x, g * xs[k][0].y);
            __half2 h1 = __floats2half2_rn(g * xs[k][0].z, g * xs[k][0].w);
            __half2 h2 = __floats2half2_rn(g * xs[k][1].x, g * xs[k][1].y);
            __half2 h3 = __floats2half2_rn(g * xs[k][1].z, g * xs[k][1].w);
            uint4 pk;
            pk.x = *reinterpret_cast<uint32_t*>(&h0);
            pk.y = *reinterpret_cast<uint32_t*>(&h1);
            pk.z = *reinterpret_cast<uint32_t*>(&h2);
            pk.w = *reinterpret_cast<uint32_t*>(&h3);
            dst[lane + 32 * k] = pk;
        }
    }
}

// ---------------- kernel 2: transpose + convert W to fp16 -----------------
__global__ void wsplit_fp16_kernel(const float* __restrict__ w) {
    __shared__ float tile[64][65];
    int e = blockIdx.z;
    int i0 = blockIdx.y * 64;
    int o0 = blockIdx.x * 64;
    int tid = threadIdx.x;     // 256
    const float* wb = w + ((size_t)e << 20);
#pragma unroll
    for (int j = 0; j < 16; j++) {
        int idx = j * 256 + tid;            // 0..4095
        int il = idx >> 6, ol = idx & 63;
        tile[il][ol] = wb[(size_t)(i0 + il) * DOUT + o0 + ol];
    }
    __syncthreads();
    __half* dst = g_wh16 + ((size_t)e << 20);
#pragma unroll
    for (int j = 0; j < 8; j++) {
        int idx = j * 256 + tid;            // 0..2047 half2 units
        int ol = idx >> 5, i2 = idx & 31;
        __half2 h = __floats2half2_rn(tile[2 * i2][ol], tile[2 * i2 + 1][ol]);
        *(__half2*)(dst + (size_t)(o0 + ol) * DIN + i0 + 2 * i2) = h;
    }
}

// ---------------- kernel 3: main GEMM (streamlined consumer) --------------
__global__ void __launch_bounds__(256, 1)
moe_gemm_kernel(float* __restrict__ out,
                const __grid_constant__ CUtensorMap tm_a,
                const __grid_constant__ CUtensorMap tm_w) {
    extern __shared__ char smem[];
    int tid = threadIdx.x;
    int wid = tid >> 5;
    int lid = tid & 31;
    int nt = blockIdx.x;           // 0..3
    int mt = blockIdx.y;           // 0..31
    int t0 = mt * BM;
    int o0 = nt * BN;

#if HAVE_TCGEN05
    // ================== tcgen05 TMA producer/consumer ====================
    uint32_t sb = smem_u32(smem);
    const uint32_t FULL0  = sb + 8;    // full[s]  = FULL0  + 8*s
    const uint32_t EMPTY0 = sb + 32;   // empty[s] = EMPTY0 + 8*s
    const uint32_t DONE   = sb + 56;
    // fp16: dtype F32, atype/btype FP16(=0), N=256, M=128
    const uint32_t IDESC = (1u << 4) | ((256 / 8) << 17) | ((128 / 16) << 24);
    const int CHUNKS = N_EXP * (DIN / BK);     // 128

    if (wid == 0) TCGEN05_ALLOC(sb, 512);
    if (tid == 0) {
#pragma unroll
        for (int s = 0; s < NSTAGE; s++) {
            MBARRIER_INIT(FULL0 + 8 * s, 1);
            MBARRIER_INIT(EMPTY0 + 8 * s, 1);
        }
        MBARRIER_INIT(DONE, 1);
    }
    __syncthreads();
    uint32_t tb;
    asm volatile("ld.shared.b32 %0, [%1];" : "=r"(tb) : "r"(sb));

    if (wid == 0) {
        // ---------------- producer: TMA loads ----------------
        int pe[NSTAGE] = {0, 0, 0};
        for (int c = 0; c < CHUNKS; c++) {
            int s = c % NSTAGE;
            int e = c >> 4, kc = c & 15;
            if (c >= NSTAGE) { MBARRIER_WAIT_PARITY(EMPTY0 + 8 * s, pe[s]); pe[s] ^= 1; }
            if (elect_one()) {
                uint32_t sbase = sb + 1024 + (uint32_t)s * STAGE_B;
                uint32_t fb = FULL0 + 8 * s;
                int cx = kc * BK;
                int ya = e * T_TOKENS + t0;
                int yb = e * DOUT + o0;
                MBARRIER_EXPECT_TX(fb, STAGE_B);
                TMA2D(sbase,              &tm_a, cx, ya,       fb);
                TMA2D(sbase + 1 * TILE_B, &tm_a, cx, ya + 128, fb);
                TMA2D(sbase + 2 * TILE_B, &tm_w, cx, yb,       fb);
                TMA2D(sbase + 3 * TILE_B, &tm_w, cx, yb + 128, fb);
            }
        }
    } else if (wid == 1) {
        // ---------------- consumer: MMA issue (N=256, hoisted descs) -----
        int pf[NSTAGE] = {0, 0, 0};
        uint64_t dA[NSTAGE][2], dB[NSTAGE];
#pragma unroll
        for (int s = 0; s < NSTAGE; s++) {
            uint32_t sbase = sb + 1024 + (uint32_t)s * STAGE_B;
            dA[s][0] = make_desc_sw128(sbase);
            dA[s][1] = make_desc_sw128(sbase + 1 * TILE_B);
            dB[s]    = make_desc_sw128(sbase + 2 * TILE_B);   // 256 rows contiguous
        }
        for (int c = 0; c < CHUNKS; c++) {
            int s = c % NSTAGE;
            MBARRIER_WAIT_PARITY(FULL0 + 8 * s, pf[s]); pf[s] ^= 1;
            if (elect_one()) {
#pragma unroll
                for (int ks = 0; ks < 4; ks++) {
                    uint64_t off = (uint64_t)(ks * 2);     // 16 fp16 = 32 B
                    uint32_t en0 = (c == 0 && ks == 0) ? 0u : 1u;
                    mma_f16_ss(tb,       dA[s][0] + off, dB[s] + off, IDESC, en0);
                    mma_f16_ss(tb + 256, dA[s][1] + off, dB[s] + off, IDESC, en0);
                }
                TCGEN05_COMMIT(EMPTY0 + 8 * s);
            }
        }
        if (elect_one()) TCGEN05_COMMIT(DONE);
    }
    // warps 2..7 fall through

    __syncthreads();                 // ensures DONE commit was issued
    MBARRIER_WAIT_PARITY(DONE, 0);
    TCGEN05_FENCE_AFTER();

    // epilogue: single TMEM read + store
    {
        int mblk = wid >> 2;
        int row = (wid & 3) * 32 + lid;
        int my_t = t0 + mblk * 128 + row;
        float* orow = out + (size_t)my_t * DOUT + o0;
#pragma unroll
        for (int q = 0; q < 8; q++) {
            uint32_t tmp[32];
            TCGEN05_LD_32X32B_X32(tmp, tb + mblk * 256 + q * 32);
            TCGEN05_WAIT_LD();
#pragma unroll
            for (int v = 0; v < 8; v++) {
                float4 f4 = make_float4(__uint_as_float(tmp[4 * v]),
                                        __uint_as_float(tmp[4 * v + 1]),
                                        __uint_as_float(tmp[4 * v + 2]),
                                        __uint_as_float(tmp[4 * v + 3]));
                ((float4*)(orow + q * 32))[v] = f4;
            }
        }
        TCGEN05_FENCE_BEFORE();
    }

    __syncthreads();
    if (tid == 0) {
#pragma unroll
        for (int s = 0; s < NSTAGE; s++) {
            MBARRIER_INVAL(FULL0 + 8 * s);
            MBARRIER_INVAL(EMPTY0 + 8 * s);
        }
        MBARRIER_INVAL(DONE);
    }
    __syncthreads();
    if (wid == 0) { TCGEN05_RELINQUISH(); TCGEN05_DEALLOC(tb, 512); }

#else
    // ================== mma.sync HMMA fallback (baseline pass) ===========
    const int wr = wid >> 1;
    const int wc = wid & 1;
    const int tg = lid >> 2;
    const int tig = lid & 3;

    for (int half = 0; half < 2; half++) {
        for (int nh = 0; nh < 2; nh++) {
            int t0h = t0 + half * 128;
            int o0h = o0 + nh * 128;

            float C[64];
#pragma unroll
            for (int i = 0; i < 64; i++) C[i] = 0.f;

            auto load_chunk = [&](int s, int c) {
                int e = c >> 5, kc = c & 31;
                const uint4* A4 = (const uint4*)(g_ah + ((size_t)e * T_TOKENS + t0h) * DIN);
                const uint4* B4 = (const uint4*)(g_wh16 + ((size_t)e << 20) + (size_t)o0h * DIN);
                char* dst = smem + s * 20480;
#pragma unroll
                for (int j = 0; j < 2; j++) {
                    int idx = j * 256 + tid;          // 0..511
                    int r2 = idx >> 2;
                    int c16 = idx & 3;
                    size_t g = (size_t)r2 * 128 + kc * 4 + c16;
                    uint32_t so = (uint32_t)r2 * 80 + c16 * 16;
                    uint4 va = A4[g];
                    uint4 vb = B4[g];
                    *(uint4*)(dst + so)         = va;
                    *(uint4*)(dst + 10240 + so) = vb;
                }
            };

            auto compute = [&](int s) {
                const char* base = smem + s * 20480;
#pragma unroll
                for (int ks = 0; ks < 2; ks++) {
                    int kb = ks * 16;
                    uint32_t a[2][4];
#pragma unroll
                    for (int m2 = 0; m2 < 2; m2++) {
                        int r0 = wr * 32 + m2 * 16 + tg;
                        const char* A0 = base + (uint32_t)r0 * 80 + (kb + tig * 2) * 2;
                        a[m2][0] = *(const uint32_t*)(A0);
                        a[m2][1] = *(const uint32_t*)(A0 + 8 * 80);
                        a[m2][2] = *(const uint32_t*)(A0 + 16);
                        a[m2][3] = *(const uint32_t*)(A0 + 8 * 80 + 16);
                    }
                    uint32_t b[8][2];
#pragma unroll
                    for (int n2 = 0; n2 < 8; n2++) {
                        int nr = wc * 64 + n2 * 8 + tg;
                        const char* B0 = base + 10240 + (uint32_t)nr * 80 + (kb + tig * 2) * 2;
                        b[n2][0] = *(const uint32_t*)(B0);
                        b[n2][1] = *(const uint32_t*)(B0 + 16);
                    }
#pragma unroll
                    for (int m2 = 0; m2 < 2; m2++)
#pragma unroll
                        for (int n2 = 0; n2 < 8; n2++)
                            mma_fp16(&C[(m2 * 8 + n2) * 4], a[m2], b[n2]);
                }
            };

            load_chunk(0, 0);
            __syncthreads();
            for (int c = 0; c < 256; c++) {
                if (c < 255) load_chunk((c + 1) & 1, c + 1);
                compute(c & 1);
                __syncthreads();
            }

#pragma unroll
            for (int m2 = 0; m2 < 2; m2++)
#pragma unroll
                for (int n2 = 0; n2 < 8; n2++) {
                    int i = (m2 * 8 + n2) * 4;
                    size_t r = (size_t)(t0h + wr * 32 + m2 * 16 + tg);
                    size_t col = (size_t)(o0h + wc * 64 + n2 * 8 + tig * 2);
                    float2 v0 = make_float2(C[i + 0], C[i + 1]);
                    float2 v1 = make_float2(C[i + 2], C[i + 3]);
                    *(float2*)&out[r * DOUT + col]       = v0;
                    *(float2*)&out[(r + 8) * DOUT + col] = v1;
                }
            __syncthreads();
        }
    }
#endif
}

// ---------------- host: tensor-map setup + launch -------------------------
typedef CUresult (*EncodeTiledFn)(
    CUtensorMap*, CUtensorMapDataType, cuuint32_t, void*,
    const cuuint64_t*, const cuuint64_t*, const cuuint32_t*, const cuuint32_t*,
    CUtensorMapInterleave, CUtensorMapSwizzle, CUtensorMapL2promotion,
    CUtensorMapFloatOOBfill);

static void make_map_2d(EncodeTiledFn enc, CUtensorMap* m, void* ptr, uint64_t rows) {
    cuuint64_t dims[2]    = {(cuuint64_t)DIN, (cuuint64_t)rows};
    cuuint64_t strides[1] = {(cuuint64_t)DIN * 2};
    cuuint32_t box[2]     = {(cuuint32_t)BK, 128};   // 64 fp16 = 128 B = SW128 span
    cuuint32_t es[2]      = {1, 1};
    enc(m, CU_TENSOR_MAP_DATA_TYPE_FLOAT16, 2, ptr, dims, strides, box, es,
        CU_TENSOR_MAP_INTERLEAVE_NONE, CU_TENSOR_MAP_SWIZZLE_128B,
        CU_TENSOR_MAP_L2_PROMOTION_L2_128B, CU_TENSOR_MAP_FLOAT_OOB_FILL_NONE);
}

extern "C" void kernel_launch(void* const* d_in, const int* in_sizes, int n_in,
                              void* d_out, int out_size) {
    const float* x  = (const float*)d_in[0];
    const float* gw = (const float*)d_in[1];
    const float* gb = (const float*)d_in[2];
    const float* w  = (const float*)d_in[3];
    float* out = (float*)d_out;

    static CUtensorMap s_maps[2];
    static bool s_init = false;
    if (!s_init) {
        void* fn = nullptr;
        cudaDriverEntryPointQueryResult qr;
        cudaGetDriverEntryPoint("cuTensorMapEncodeTiled", &fn, cudaEnableDefault, &qr);
        EncodeTiledFn enc = (EncodeTiledFn)fn;
        void *pa, *pw;
        cudaGetSymbolAddress(&pa, g_ah);
        cudaGetSymbolAddress(&pw, g_wh16);
        make_map_2d(enc, &s_maps[0], pa, (uint64_t)N_EXP * T_TOKENS);
        make_map_2d(enc, &s_maps[1], pw, (uint64_t)N_EXP * DOUT);
        s_init = true;
    }

    gate_prescale_kernel<<<T_TOKENS / 8, 256>>>(x, gw, gb);
    wsplit_fp16_kernel<<<dim3(DOUT / 64, DIN / 64, N_EXP), 256>>>(w);

    cudaFuncSetAttribute(moe_gemm_kernel,
                         cudaFuncAttributeMaxDynamicSharedMemorySize, GEMM_SMEM);
    moe_gemm_kernel<<<dim3(DOUT / BN, T_TOKENS / BM), 256, GEMM_SMEM>>>(
        out, s_maps[0], s_maps[1]);
}